// round 15
// baseline (speedup 1.0000x reference)
#include <cuda_runtime.h>
#include <cuda_fp16.h>
#include <cstdint>

#define B_DIM 1024
#define L_DIM 200
#define C_DIM 384
#define OUT_D 10000
#define M1    (B_DIM * L_DIM)     // 204800

#define KT    32                  // k-tile
#define LDSX  40                  // smem row stride in halves (conflict-free)
#define NTB   64                  // CTA n-tile
#define NBLK1 6                   // GEMM1 n-blocks (384/64)

// ---- device scratch (static allocations only) ------------------------------
__device__ __half g_h[(size_t)M1 * C_DIM];          // 157 MB fp16 h
__device__ __half g_cvh[B_DIM * C_DIM];             // pooled code vectors (fp16)
__device__ __half g_wfc[C_DIM * C_DIM];             // W_fc in fp16
__device__ __half g_wout[(size_t)OUT_D * C_DIM];    // W_out in fp16
__device__ float  g_spart[NBLK1 * (size_t)M1];      // per-n-block score partials

// ---- helpers ---------------------------------------------------------------
__device__ __forceinline__ void ldsm4(uint32_t (&r)[4], uint32_t saddr) {
    asm volatile("ldmatrix.sync.aligned.m8n8.x4.shared.b16 {%0,%1,%2,%3}, [%4];\n"
                 : "=r"(r[0]), "=r"(r[1]), "=r"(r[2]), "=r"(r[3]) : "r"(saddr));
}

__device__ __forceinline__ void mma16816(float (&c)[4], const uint32_t (&a)[4],
                                         uint32_t b0, uint32_t b1) {
    asm volatile(
        "mma.sync.aligned.m16n8k16.row.col.f32.f16.f16.f32 "
        "{%0,%1,%2,%3}, {%4,%5,%6,%7}, {%8,%9}, {%0,%1,%2,%3};\n"
        : "+f"(c[0]), "+f"(c[1]), "+f"(c[2]), "+f"(c[3])
        : "r"(a[0]), "r"(a[1]), "r"(a[2]), "r"(a[3]), "r"(b0), "r"(b1));
}

// cp.async 16B with zero-fill when szb==0
__device__ __forceinline__ void cp_async16(uint32_t dst, const void* src, int szb) {
    asm volatile("cp.async.ca.shared.global [%0], [%1], 16, %2;\n"
                 :: "r"(dst), "l"(src), "r"(szb) : "memory");
}
#define CP_ASYNC_COMMIT() asm volatile("cp.async.commit_group;\n" ::: "memory")
#define CP_ASYNC_WAIT0()  asm volatile("cp.async.wait_group 0;\n" ::: "memory")

// tanh: inputs have |x| ~ 0.02 (std); polynomial exact to ~1e-9 for |x|<=0.25,
// accurate tanhf fallback for the (never-in-practice) tail.
__device__ __forceinline__ float tanh_fast(float x) {
    float x2 = x * x;
    float p = fmaf(x2, fmaf(x2, 0.133333333f, -0.333333333f), 1.0f);
    float v = x * p;
    if (fabsf(x) > 0.25f) v = tanhf(x);
    return v;
}

// ---- fp32 -> fp16 weight conversion ---------------------------------------
__global__ __launch_bounds__(256)
void f2h_kernel(const float* __restrict__ s, __half* __restrict__ d, int n4) {
    int i = blockIdx.x * blockDim.x + threadIdx.x;
    if (i < n4) {
        float4 f = reinterpret_cast<const float4*>(s)[i];
        __half2 h0 = __floats2half2_rn(f.x, f.y);
        __half2 h1 = __floats2half2_rn(f.z, f.w);
        __half2* dp = reinterpret_cast<__half2*>(d) + 2 * i;
        dp[0] = h0; dp[1] = h1;
    }
}

// ---------------------------------------------------------------------------
// Tensor-core GEMM, CTA tile 128 x 64, k-tile 32, double-buffered.
//   GATHER=1 (GEMM1): A gathered fp32->fp16 from embedding tables (register
//       staging); B via cp.async. Epilogue: tanh, fp16 h store, fused
//       per-n-block score partials (deterministic).
//   GATHER=0 (GEMM2): A = fp16 cv via cp.async; B via cp.async.
//       Epilogue: +bias, fp32 out, n<Nw guard.
// 8 warps as 4(m) x 2(n); warp tile 32x32. 3 CTAs/SM (smem ~31 KB, regs<=85).
// ---------------------------------------------------------------------------
template <int GATHER>
__global__ __launch_bounds__(256, 3)
void mma_gemm(const __half* __restrict__ Ah,
              const int* __restrict__ starts, const int* __restrict__ paths,
              const int* __restrict__ ends,
              const float* __restrict__ node_emb, const float* __restrict__ path_emb,
              const __half* __restrict__ Bw, const float* __restrict__ bias,
              const float* __restrict__ a_vec,
              void* __restrict__ Cout, int Nw) {
    __shared__ __align__(16) __half sA[2][128 * LDSX];
    __shared__ __align__(16) __half sB[2][NTB * LDSX];
    __shared__ float sAvec[NTB];
    __shared__ float sScore[2][128];
    const int tid = threadIdx.x;
    const int m0 = blockIdx.y * 128, n0 = blockIdx.x * NTB;

    // -------- loader mappings
    // A (GATHER): 2 thr/row, 16 halves each (fp32 load + convert)
    const int ar = tid >> 1, aseg = (tid & 1) * 16;
    int i_s = 0, i_p = 0, i_e = 0;
    if (GATHER) { int m = m0 + ar; i_s = starts[m]; i_p = paths[m]; i_e = ends[m]; }
    // B: 4 thr/row, 8 halves (16 B) each
    const int br = tid >> 2, bseg = (tid & 3) * 8;
    const int nr = n0 + br;
    const int bsz = (nr < Nw) ? 16 : 0;
    const __half* bsrc_row = Bw + (size_t)((nr < Nw) ? nr : 0) * C_DIM + bseg;

    float4 fA[4];

    auto loadA_regs = [&](int k0) {
        const float* ap;
        int k = k0 + aseg;
        if (k < 128)      ap = node_emb + (size_t)i_s * 128 + k;
        else if (k < 256) ap = path_emb + (size_t)i_p * 128 + (k - 128);
        else              ap = node_emb + (size_t)i_e * 128 + (k - 256);
        #pragma unroll
        for (int q = 0; q < 4; q++) fA[q] = reinterpret_cast<const float4*>(ap)[q];
    };
    auto storeA = [&](int buf) {
        __half2 h[8];
        #pragma unroll
        for (int q = 0; q < 4; q++) {
            h[2 * q]     = __floats2half2_rn(fA[q].x, fA[q].y);
            h[2 * q + 1] = __floats2half2_rn(fA[q].z, fA[q].w);
        }
        uint4* pa = reinterpret_cast<uint4*>(&sA[buf][ar * LDSX + aseg]);
        pa[0] = make_uint4(*(uint32_t*)&h[0], *(uint32_t*)&h[1],
                           *(uint32_t*)&h[2], *(uint32_t*)&h[3]);
        pa[1] = make_uint4(*(uint32_t*)&h[4], *(uint32_t*)&h[5],
                           *(uint32_t*)&h[6], *(uint32_t*)&h[7]);
    };
    auto cpB = [&](int buf, int k0) {
        uint32_t dst = (uint32_t)__cvta_generic_to_shared(
            &sB[buf][br * LDSX + bseg]);
        cp_async16(dst, bsrc_row + k0, bsz);
    };
    auto cpA = [&](int buf, int k0) {   // GEMM2 only: fp16 A, 2 thr/row, 32 B
        const int row = tid >> 1, seg = (tid & 1) * 16;
        uint32_t dst = (uint32_t)__cvta_generic_to_shared(
            &sA[buf][row * LDSX + seg]);
        const __half* src = Ah + (size_t)(m0 + row) * C_DIM + k0 + seg;
        cp_async16(dst, src, 16);
        cp_async16(dst + 16, src + 8, 16);
    };

    // -------- compute mapping
    const int lane = tid & 31, warp = tid >> 5;
    const int wm = warp & 3, wn = warp >> 2;       // 4 x 2 warp grid
    const int g = lane >> 2, t4 = lane & 3;
    const int a_row = (lane & 7) + ((lane >> 3) & 1) * 8;
    const int a_ko  = (lane >> 4) * 8;
    const int b_row = (lane & 7) + ((lane >> 4) & 1) * 8;
    const int b_ko  = ((lane >> 3) & 1) * 8;

    float acc[2][4][4];
    #pragma unroll
    for (int i = 0; i < 2; i++)
        #pragma unroll
        for (int j = 0; j < 4; j++)
            #pragma unroll
            for (int q = 0; q < 4; q++) acc[i][j][q] = 0.f;

    if (GATHER && tid < NTB) sAvec[tid] = a_vec[n0 + tid];

    // -------- prologue: stage k0=0 into buf 0
    if (GATHER) { loadA_regs(0); storeA(0); } else { cpA(0, 0); }
    cpB(0, 0);
    CP_ASYNC_COMMIT();
    CP_ASYNC_WAIT0();
    __syncthreads();

    const int KSTEPS = C_DIM / KT;   // 12
    for (int s = 0; s < KSTEPS; ++s) {
        const int buf = s & 1;
        // prefetch next stage
        if (s + 1 < KSTEPS) {
            const int kn = (s + 1) * KT;
            if (GATHER) loadA_regs(kn); else cpA(buf ^ 1, kn);
            cpB(buf ^ 1, kn);
            CP_ASYNC_COMMIT();
        }

        #pragma unroll
        for (int ks = 0; ks < 2; ++ks) {
            const int ko = ks * 16;
            uint32_t af[2][4], bf[2][4];
            #pragma unroll
            for (int i = 0; i < 2; i++) {
                uint32_t ad = (uint32_t)__cvta_generic_to_shared(
                    &sA[buf][(wm * 32 + i * 16 + a_row) * LDSX + ko + a_ko]);
                ldsm4(af[i], ad);
            }
            #pragma unroll
            for (int p = 0; p < 2; p++) {
                uint32_t bd = (uint32_t)__cvta_generic_to_shared(
                    &sB[buf][(wn * 32 + p * 16 + b_row) * LDSX + ko + b_ko]);
                ldsm4(bf[p], bd);
            }
            #pragma unroll
            for (int i = 0; i < 2; i++)
                #pragma unroll
                for (int j = 0; j < 4; j++)
                    mma16816(acc[i][j], af[i],
                             bf[j >> 1][(j & 1) * 2], bf[j >> 1][(j & 1) * 2 + 1]);
        }
        if (s + 1 < KSTEPS) {
            if (GATHER) storeA(buf ^ 1);
            CP_ASYNC_WAIT0();
        }
        __syncthreads();
    }

    // -------- epilogue
    if (GATHER) {
        float sc[2][2] = {{0.f, 0.f}, {0.f, 0.f}};
        #pragma unroll
        for (int i = 0; i < 2; i++) {
            #pragma unroll
            for (int j = 0; j < 4; j++) {
                const int r = m0 + wm * 32 + i * 16 + g;
                const int cl = wn * 32 + j * 8 + t4 * 2;
                const int c = n0 + cl;
                __half* C = (__half*)Cout;
                float v0 = tanh_fast(acc[i][j][0]);
                float v1 = tanh_fast(acc[i][j][1]);
                float v2 = tanh_fast(acc[i][j][2]);
                float v3 = tanh_fast(acc[i][j][3]);
                float a0 = sAvec[cl], a1 = sAvec[cl + 1];
                sc[i][0] = fmaf(v0, a0, fmaf(v1, a1, sc[i][0]));
                sc[i][1] = fmaf(v2, a0, fmaf(v3, a1, sc[i][1]));
                *reinterpret_cast<__half2*>(&C[(size_t)r * Nw + c]) =
                    __floats2half2_rn(v0, v1);
                *reinterpret_cast<__half2*>(&C[(size_t)(r + 8) * Nw + c]) =
                    __floats2half2_rn(v2, v3);
            }
        }
        // reduce score partials over the quad (4 lanes share a row-pair)
        #pragma unroll
        for (int i = 0; i < 2; i++)
            #pragma unroll
            for (int rh = 0; rh < 2; rh++) {
                sc[i][rh] += __shfl_xor_sync(0xffffffffu, sc[i][rh], 1);
                sc[i][rh] += __shfl_xor_sync(0xffffffffu, sc[i][rh], 2);
            }
        if (t4 == 0) {
            #pragma unroll
            for (int i = 0; i < 2; i++)
                #pragma unroll
                for (int rh = 0; rh < 2; rh++)
                    sScore[wn][wm * 32 + i * 16 + g + rh * 8] = sc[i][rh];
        }
        __syncthreads();
        if (tid < 128)
            g_spart[(size_t)blockIdx.x * M1 + m0 + tid] =
                sScore[0][tid] + sScore[1][tid];
    } else {
        float* C = (float*)Cout;
        #pragma unroll
        for (int i = 0; i < 2; i++) {
            #pragma unroll
            for (int j = 0; j < 4; j++) {
                const int r = m0 + wm * 32 + i * 16 + g;
                const int c = n0 + wn * 32 + j * 8 + t4 * 2;
                if (c < Nw)     C[(size_t)r * Nw + c]           = acc[i][j][0] + bias[c];
                if (c + 1 < Nw) C[(size_t)r * Nw + c + 1]       = acc[i][j][1] + bias[c + 1];
                if (c < Nw)     C[(size_t)(r + 8) * Nw + c]     = acc[i][j][2] + bias[c];
                if (c + 1 < Nw) C[(size_t)(r + 8) * Nw + c + 1] = acc[i][j][3] + bias[c + 1];
            }
        }
    }
}

// ---------------------------------------------------------------------------
// Attention: sum 6 score partials, softmax over L, single streaming h pass,
// emit cv directly in fp16 (consumed by GEMM2 via cp.async).
// ---------------------------------------------------------------------------
__global__ __launch_bounds__(256)
void attn_kernel(void) {
    __shared__ float s_w[L_DIM];
    __shared__ float red[8];
    const int b = blockIdx.x, tid = threadIdx.x;
    const int lane = tid & 31, warp = tid >> 5;

    float v = -1e30f;
    if (tid < L_DIM) {
        size_t m = (size_t)b * L_DIM + tid;
        float t = 0.f;
        #pragma unroll
        for (int p = 0; p < NBLK1; p++) t += g_spart[(size_t)p * M1 + m];
        v = t;
    }
    float mx = v;
    #pragma unroll
    for (int o = 16; o; o >>= 1) mx = fmaxf(mx, __shfl_xor_sync(0xffffffffu, mx, o));
    if (lane == 0) red[warp] = mx;
    __syncthreads();
    if (tid == 0) {
        float t = red[0];
        #pragma unroll
        for (int i = 1; i < 8; i++) t = fmaxf(t, red[i]);
        red[0] = t;
    }
    __syncthreads();
    const float gmax = red[0];
    __syncthreads();
    float e = (tid < L_DIM) ? expf(v - gmax) : 0.f;
    float sm = e;
    #pragma unroll
    for (int o = 16; o; o >>= 1) sm += __shfl_xor_sync(0xffffffffu, sm, o);
    if (lane == 0) red[warp] = sm;
    __syncthreads();
    if (tid == 0) {
        float t = 0.f;
        #pragma unroll
        for (int i = 0; i < 8; i++) t += red[i];
        red[0] = t;
    }
    __syncthreads();
    const float inv = 1.0f / red[0];
    if (tid < L_DIM) s_w[tid] = e * inv;
    __syncthreads();

    // single streaming pass: cv[b,c] = sum_l w[l] * h[b,l,c]
    if (tid < C_DIM / 2) {
        const __half2* hb2 = reinterpret_cast<const __half2*>(
            g_h + (size_t)b * L_DIM * C_DIM);
        float ax = 0.f, ay = 0.f;
        #pragma unroll 8
        for (int l = 0; l < L_DIM; l++) {
            float w = s_w[l];
            float2 f = __half22float2(hb2[l * (C_DIM / 2) + tid]);
            ax = fmaf(w, f.x, ax);
            ay = fmaf(w, f.y, ay);
        }
        *reinterpret_cast<__half2*>(&g_cvh[b * C_DIM + 2 * tid]) =
            __floats2half2_rn(ax, ay);
    }
}

// ---------------------------------------------------------------------------
extern "C" void kernel_launch(void* const* d_in, const int* in_sizes, int n_in,
                              void* d_out, int out_size) {
    const int*   starts   = (const int*)  d_in[0];
    const int*   paths    = (const int*)  d_in[1];
    const int*   ends     = (const int*)  d_in[2];
    const float* node_emb = (const float*)d_in[3];
    const float* path_emb = (const float*)d_in[4];
    const float* W_fc     = (const float*)d_in[5];
    const float* a_vec    = (const float*)d_in[6];
    const float* W_out    = (const float*)d_in[7];
    const float* b_out    = (const float*)d_in[8];

    __half *p_h, *p_wfc, *p_wout, *p_cvh;
    cudaGetSymbolAddress((void**)&p_h,    g_h);
    cudaGetSymbolAddress((void**)&p_cvh,  g_cvh);
    cudaGetSymbolAddress((void**)&p_wfc,  g_wfc);
    cudaGetSymbolAddress((void**)&p_wout, g_wout);

    // 0) weight conversions to fp16
    f2h_kernel<<<(C_DIM * C_DIM / 4 + 255) / 256, 256>>>(W_fc, p_wfc, C_DIM * C_DIM / 4);
    f2h_kernel<<<(OUT_D * C_DIM / 4 + 255) / 256, 256>>>(W_out, p_wout, OUT_D * C_DIM / 4);

    // 1) h = tanh(gather(ctx) @ W_fc^T) -> fp16, plus per-n-block score partials
    mma_gemm<1><<<dim3(NBLK1, M1 / 128), 256>>>(
        nullptr, starts, paths, ends, node_emb, path_emb,
        p_wfc, nullptr, a_vec, (void*)p_h, C_DIM);

    // 2) softmax + attention pooling -> cv fp16 [1024 x 384] (single h pass)
    attn_kernel<<<B_DIM, 256>>>();

    // 3) out = cv @ W_out^T + b_out -> fp32 [1024 x 10000]
    mma_gemm<0><<<dim3((OUT_D + NTB - 1) / NTB, B_DIM / 128), 256>>>(
        p_cvh, nullptr, nullptr, nullptr, nullptr, nullptr,
        p_wout, b_out, nullptr, d_out, OUT_D);
}

// round 16
// speedup vs baseline: 1.2846x; 1.2846x over previous
#include <cuda_runtime.h>
#include <cuda_fp16.h>
#include <cstdint>

#define B_DIM 1024
#define L_DIM 200
#define C_DIM 384
#define OUT_D 10000
#define M1    (B_DIM * L_DIM)     // 204800

#define KT  32                    // k-tile
#define LDSX 40                   // smem row stride in halves (conflict-free)
#define NBLK1 3                   // GEMM1 n-blocks (384/128)

// ---- device scratch (static allocations only) ------------------------------
__device__ __half g_h[(size_t)M1 * C_DIM];          // 157 MB fp16 h
__device__ __half g_cvh[B_DIM * C_DIM];             // pooled code vectors (fp16)
__device__ __half g_wfc[C_DIM * C_DIM];             // W_fc in fp16
__device__ __half g_wout[(size_t)OUT_D * C_DIM];    // W_out in fp16
__device__ float  g_spart[NBLK1 * (size_t)M1];      // per-n-block score partials

// ---- helpers ---------------------------------------------------------------
__device__ __forceinline__ void ldsm4(uint32_t (&r)[4], uint32_t saddr) {
    asm volatile("ldmatrix.sync.aligned.m8n8.x4.shared.b16 {%0,%1,%2,%3}, [%4];\n"
                 : "=r"(r[0]), "=r"(r[1]), "=r"(r[2]), "=r"(r[3]) : "r"(saddr));
}

__device__ __forceinline__ void mma16816(float (&c)[4], const uint32_t (&a)[4],
                                         uint32_t b0, uint32_t b1) {
    asm volatile(
        "mma.sync.aligned.m16n8k16.row.col.f32.f16.f16.f32 "
        "{%0,%1,%2,%3}, {%4,%5,%6,%7}, {%8,%9}, {%0,%1,%2,%3};\n"
        : "+f"(c[0]), "+f"(c[1]), "+f"(c[2]), "+f"(c[3])
        : "r"(a[0]), "r"(a[1]), "r"(a[2]), "r"(a[3]), "r"(b0), "r"(b1));
}

// cp.async 16B with zero-fill when szb==0
__device__ __forceinline__ void cp_async16(uint32_t dst, const void* src, int szb) {
    asm volatile("cp.async.ca.shared.global [%0], [%1], 16, %2;\n"
                 :: "r"(dst), "l"(src), "r"(szb) : "memory");
}
#define CP_ASYNC_COMMIT() asm volatile("cp.async.commit_group;\n" ::: "memory")
#define CP_ASYNC_WAIT0()  asm volatile("cp.async.wait_group 0;\n" ::: "memory")

// tanh: inputs have |x| ~ 0.02 (std); polynomial exact to ~1e-9 for |x|<=0.25,
// accurate tanhf fallback for the (never-in-practice) tail.
__device__ __forceinline__ float tanh_fast(float x) {
    float x2 = x * x;
    float p = fmaf(x2, fmaf(x2, 0.133333333f, -0.333333333f), 1.0f);
    float v = x * p;
    if (fabsf(x) > 0.25f) v = tanhf(x);
    return v;
}

// ---- fp32 -> fp16 weight conversion ---------------------------------------
__global__ __launch_bounds__(256)
void f2h_kernel(const float* __restrict__ s, __half* __restrict__ d, int n4) {
    int i = blockIdx.x * blockDim.x + threadIdx.x;
    if (i < n4) {
        float4 f = reinterpret_cast<const float4*>(s)[i];
        __half2 h0 = __floats2half2_rn(f.x, f.y);
        __half2 h1 = __floats2half2_rn(f.z, f.w);
        __half2* dp = reinterpret_cast<__half2*>(d) + 2 * i;
        dp[0] = h0; dp[1] = h1;
    }
}

// ---------------------------------------------------------------------------
// Tensor-core GEMM: C[m,n] = op( sum_k A[m,k] * Bw16[n,k] )
//   GATHER=1 (GEMM1): A rows gathered fp32->fp16 from embedding tables
//       (register staging); B = W_fc fp16 via cp.async. Epilogue: tanh,
//       fp16 h store, fused per-n-block score partials (deterministic).
//   GATHER=0 (GEMM2): A = fp16 cv via cp.async; B = W_out fp16 via cp.async.
//       Epilogue: +bias, fp32 out, n<Nw guard.
// CTA tile 128x128, k-tile 32, 8 warps as 4(m) x 2(n), warp tile 32x64.
// __launch_bounds__(256,2) pins regs <= 128 so 2 CTAs/SM residency holds.
// ---------------------------------------------------------------------------
template <int GATHER>
__global__ __launch_bounds__(256, 2)
void mma_gemm(const __half* __restrict__ Ah,
              const int* __restrict__ starts, const int* __restrict__ paths,
              const int* __restrict__ ends,
              const float* __restrict__ node_emb, const float* __restrict__ path_emb,
              const __half* __restrict__ Bw, const float* __restrict__ bias,
              const float* __restrict__ a_vec,
              void* __restrict__ Cout, int Nw) {
    __shared__ __align__(16) __half sA[2][128 * LDSX];
    __shared__ __align__(16) __half sB[2][128 * LDSX];
    __shared__ float sAvec[128];
    __shared__ float sScore[2][128];
    const int tid = threadIdx.x;
    const int m0 = blockIdx.y * 128, n0 = blockIdx.x * 128;

    // -------- loader mapping (256 thr: 2 threads per row, 16 halves each)
    const int ar = tid >> 1, aseg = (tid & 1) * 16;
    const int br = ar,       bseg = aseg;
    int i_s = 0, i_p = 0, i_e = 0;
    if (GATHER) { int m = m0 + ar; i_s = starts[m]; i_p = paths[m]; i_e = ends[m]; }
    const int nr = n0 + br;
    const int bsz = (nr < Nw) ? 16 : 0;
    const __half* bsrc_row = Bw + (size_t)((nr < Nw) ? nr : 0) * C_DIM + bseg;

    float4 fA[4];

    auto loadA_regs = [&](int k0) {      // GEMM1: fp32 gather
        const float* ap;
        int k = k0 + aseg;
        if (k < 128)      ap = node_emb + (size_t)i_s * 128 + k;
        else if (k < 256) ap = path_emb + (size_t)i_p * 128 + (k - 128);
        else              ap = node_emb + (size_t)i_e * 128 + (k - 256);
        #pragma unroll
        for (int q = 0; q < 4; q++) fA[q] = reinterpret_cast<const float4*>(ap)[q];
    };
    auto storeA = [&](int buf) {
        __half2 h[8];
        #pragma unroll
        for (int q = 0; q < 4; q++) {
            h[2 * q]     = __floats2half2_rn(fA[q].x, fA[q].y);
            h[2 * q + 1] = __floats2half2_rn(fA[q].z, fA[q].w);
        }
        uint4* pa = reinterpret_cast<uint4*>(&sA[buf][ar * LDSX + aseg]);
        pa[0] = make_uint4(*(uint32_t*)&h[0], *(uint32_t*)&h[1],
                           *(uint32_t*)&h[2], *(uint32_t*)&h[3]);
        pa[1] = make_uint4(*(uint32_t*)&h[4], *(uint32_t*)&h[5],
                           *(uint32_t*)&h[6], *(uint32_t*)&h[7]);
    };
    auto cpA = [&](int buf, int k0) {    // GEMM2: fp16 A
        uint32_t dst = (uint32_t)__cvta_generic_to_shared(
            &sA[buf][ar * LDSX + aseg]);
        const __half* src = Ah + (size_t)(m0 + ar) * C_DIM + k0 + aseg;
        cp_async16(dst, src, 16);
        cp_async16(dst + 16, src + 8, 16);
    };
    auto cpB = [&](int buf, int k0) {
        uint32_t dst = (uint32_t)__cvta_generic_to_shared(
            &sB[buf][br * LDSX + bseg]);
        cp_async16(dst, bsrc_row + k0, bsz);
        cp_async16(dst + 16, bsrc_row + k0 + 8, bsz);
    };

    // -------- compute mapping
    const int lane = tid & 31, warp = tid >> 5;
    const int wm = warp & 3, wn = warp >> 2;       // 4 x 2 warp grid
    const int g = lane >> 2, t4 = lane & 3;
    const int a_row = (lane & 7) + ((lane >> 3) & 1) * 8;
    const int a_ko  = (lane >> 4) * 8;
    const int b_row = (lane & 7) + ((lane >> 4) & 1) * 8;
    const int b_ko  = ((lane >> 3) & 1) * 8;

    float acc[2][8][4];
    #pragma unroll
    for (int i = 0; i < 2; i++)
        #pragma unroll
        for (int j = 0; j < 8; j++)
            #pragma unroll
            for (int q = 0; q < 4; q++) acc[i][j][q] = 0.f;

    if (GATHER && tid < 128) sAvec[tid] = a_vec[n0 + tid];

    // -------- prologue: stage k0=0 into buf 0
    if (GATHER) { loadA_regs(0); storeA(0); } else { cpA(0, 0); }
    cpB(0, 0);
    CP_ASYNC_COMMIT();
    CP_ASYNC_WAIT0();
    __syncthreads();

    const int KSTEPS = C_DIM / KT;   // 12
    for (int s = 0; s < KSTEPS; ++s) {
        const int buf = s & 1;
        if (s + 1 < KSTEPS) {
            const int kn = (s + 1) * KT;
            if (GATHER) loadA_regs(kn); else cpA(buf ^ 1, kn);
            cpB(buf ^ 1, kn);
            CP_ASYNC_COMMIT();
        }

        #pragma unroll
        for (int ks = 0; ks < 2; ++ks) {
            const int ko = ks * 16;
            uint32_t af[2][4], bf[4][4];
            #pragma unroll
            for (int i = 0; i < 2; i++) {
                uint32_t ad = (uint32_t)__cvta_generic_to_shared(
                    &sA[buf][(wm * 32 + i * 16 + a_row) * LDSX + ko + a_ko]);
                ldsm4(af[i], ad);
            }
            #pragma unroll
            for (int p = 0; p < 4; p++) {
                uint32_t bd = (uint32_t)__cvta_generic_to_shared(
                    &sB[buf][(wn * 64 + p * 16 + b_row) * LDSX + ko + b_ko]);
                ldsm4(bf[p], bd);
            }
            #pragma unroll
            for (int i = 0; i < 2; i++)
                #pragma unroll
                for (int j = 0; j < 8; j++)
                    mma16816(acc[i][j], af[i],
                             bf[j >> 1][(j & 1) * 2], bf[j >> 1][(j & 1) * 2 + 1]);
        }
        if (s + 1 < KSTEPS) {
            if (GATHER) storeA(buf ^ 1);
            CP_ASYNC_WAIT0();
        }
        __syncthreads();
    }

    // -------- epilogue
    if (GATHER) {
        float sc[2][2] = {{0.f, 0.f}, {0.f, 0.f}};   // score partials
        #pragma unroll
        for (int i = 0; i < 2; i++) {
            #pragma unroll
            for (int j = 0; j < 8; j++) {
                const int r = m0 + wm * 32 + i * 16 + g;
                const int cl = wn * 64 + j * 8 + t4 * 2;
                const int c = n0 + cl;
                __half* C = (__half*)Cout;
                float v0 = tanh_fast(acc[i][j][0]);
                float v1 = tanh_fast(acc[i][j][1]);
                float v2 = tanh_fast(acc[i][j][2]);
                float v3 = tanh_fast(acc[i][j][3]);
                float a0 = sAvec[cl], a1 = sAvec[cl + 1];
                sc[i][0] = fmaf(v0, a0, fmaf(v1, a1, sc[i][0]));
                sc[i][1] = fmaf(v2, a0, fmaf(v3, a1, sc[i][1]));
                *reinterpret_cast<__half2*>(&C[(size_t)r * Nw + c]) =
                    __floats2half2_rn(v0, v1);
                *reinterpret_cast<__half2*>(&C[(size_t)(r + 8) * Nw + c]) =
                    __floats2half2_rn(v2, v3);
            }
        }
        // reduce score partials over the quad (4 lanes share a row-pair)
        #pragma unroll
        for (int i = 0; i < 2; i++)
            #pragma unroll
            for (int rh = 0; rh < 2; rh++) {
                sc[i][rh] += __shfl_xor_sync(0xffffffffu, sc[i][rh], 1);
                sc[i][rh] += __shfl_xor_sync(0xffffffffu, sc[i][rh], 2);
            }
        if (t4 == 0) {
            #pragma unroll
            for (int i = 0; i < 2; i++)
                #pragma unroll
                for (int rh = 0; rh < 2; rh++)
                    sScore[wn][wm * 32 + i * 16 + g + rh * 8] = sc[i][rh];
        }
        __syncthreads();
        if (tid < 128)
            g_spart[(size_t)blockIdx.x * M1 + m0 + tid] =
                sScore[0][tid] + sScore[1][tid];
    } else {
        float* C = (float*)Cout;
        #pragma unroll
        for (int i = 0; i < 2; i++) {
            #pragma unroll
            for (int j = 0; j < 8; j++) {
                const int r = m0 + wm * 32 + i * 16 + g;
                const int c = n0 + wn * 64 + j * 8 + t4 * 2;
                if (c < Nw)     C[(size_t)r * Nw + c]           = acc[i][j][0] + bias[c];
                if (c + 1 < Nw) C[(size_t)r * Nw + c + 1]       = acc[i][j][1] + bias[c + 1];
                if (c < Nw)     C[(size_t)(r + 8) * Nw + c]     = acc[i][j][2] + bias[c];
                if (c + 1 < Nw) C[(size_t)(r + 8) * Nw + c + 1] = acc[i][j][3] + bias[c + 1];
            }
        }
    }
}

// ---------------------------------------------------------------------------
// Attention: sum 3 score partials, softmax over L, single streaming h pass,
// emit cv in fp16 (consumed by GEMM2 via cp.async).
// ---------------------------------------------------------------------------
__global__ __launch_bounds__(256)
void attn_kernel(void) {
    __shared__ float s_w[L_DIM];
    __shared__ float red[8];
    const int b = blockIdx.x, tid = threadIdx.x;
    const int lane = tid & 31, warp = tid >> 5;

    float v = -1e30f;
    if (tid < L_DIM) {
        size_t m = (size_t)b * L_DIM + tid;
        float t = 0.f;
        #pragma unroll
        for (int p = 0; p < NBLK1; p++) t += g_spart[(size_t)p * M1 + m];
        v = t;
    }
    float mx = v;
    #pragma unroll
    for (int o = 16; o; o >>= 1) mx = fmaxf(mx, __shfl_xor_sync(0xffffffffu, mx, o));
    if (lane == 0) red[warp] = mx;
    __syncthreads();
    if (tid == 0) {
        float t = red[0];
        #pragma unroll
        for (int i = 1; i < 8; i++) t = fmaxf(t, red[i]);
        red[0] = t;
    }
    __syncthreads();
    const float gmax = red[0];
    __syncthreads();
    float e = (tid < L_DIM) ? expf(v - gmax) : 0.f;
    float sm = e;
    #pragma unroll
    for (int o = 16; o; o >>= 1) sm += __shfl_xor_sync(0xffffffffu, sm, o);
    if (lane == 0) red[warp] = sm;
    __syncthreads();
    if (tid == 0) {
        float t = 0.f;
        #pragma unroll
        for (int i = 0; i < 8; i++) t += red[i];
        red[0] = t;
    }
    __syncthreads();
    const float inv = 1.0f / red[0];
    if (tid < L_DIM) s_w[tid] = e * inv;
    __syncthreads();

    // single streaming pass: cv[b,c] = sum_l w[l] * h[b,l,c]
    if (tid < C_DIM / 2) {
        const __half2* hb2 = reinterpret_cast<const __half2*>(
            g_h + (size_t)b * L_DIM * C_DIM);
        float ax = 0.f, ay = 0.f;
        #pragma unroll 8
        for (int l = 0; l < L_DIM; l++) {
            float w = s_w[l];
            float2 f = __half22float2(hb2[l * (C_DIM / 2) + tid]);
            ax = fmaf(w, f.x, ax);
            ay = fmaf(w, f.y, ay);
        }
        *reinterpret_cast<__half2*>(&g_cvh[b * C_DIM + 2 * tid]) =
            __floats2half2_rn(ax, ay);
    }
}

// ---------------------------------------------------------------------------
extern "C" void kernel_launch(void* const* d_in, const int* in_sizes, int n_in,
                              void* d_out, int out_size) {
    const int*   starts   = (const int*)  d_in[0];
    const int*   paths    = (const int*)  d_in[1];
    const int*   ends     = (const int*)  d_in[2];
    const float* node_emb = (const float*)d_in[3];
    const float* path_emb = (const float*)d_in[4];
    const float* W_fc     = (const float*)d_in[5];
    const float* a_vec    = (const float*)d_in[6];
    const float* W_out    = (const float*)d_in[7];
    const float* b_out    = (const float*)d_in[8];

    __half *p_h, *p_wfc, *p_wout, *p_cvh;
    cudaGetSymbolAddress((void**)&p_h,    g_h);
    cudaGetSymbolAddress((void**)&p_cvh,  g_cvh);
    cudaGetSymbolAddress((void**)&p_wfc,  g_wfc);
    cudaGetSymbolAddress((void**)&p_wout, g_wout);

    // 0) weight conversions to fp16
    f2h_kernel<<<(C_DIM * C_DIM / 4 + 255) / 256, 256>>>(W_fc, p_wfc, C_DIM * C_DIM / 4);
    f2h_kernel<<<(OUT_D * C_DIM / 4 + 255) / 256, 256>>>(W_out, p_wout, OUT_D * C_DIM / 4);

    // 1) h = tanh(gather(ctx) @ W_fc^T) -> fp16, plus per-n-block score partials
    mma_gemm<1><<<dim3(NBLK1, M1 / 128), 256>>>(
        nullptr, starts, paths, ends, node_emb, path_emb,
        p_wfc, nullptr, a_vec, (void*)p_h, C_DIM);

    // 2) softmax + attention pooling -> cv fp16 [1024 x 384] (single h pass)
    attn_kernel<<<B_DIM, 256>>>();

    // 3) out = cv @ W_out^T + b_out -> fp32 [1024 x 10000]
    mma_gemm<0><<<dim3((OUT_D + 127) / 128, B_DIM / 128), 256>>>(
        p_cvh, nullptr, nullptr, nullptr, nullptr, nullptr,
        p_wout, b_out, nullptr, d_out, OUT_D);
}